// round 6
// baseline (speedup 1.0000x reference)
#include <cuda_runtime.h>
#include <cuda_fp16.h>
#include <cstdint>

// Problem constants
#define BB 4096
#define SS 31
#define CC 512
#define HH 8
#define HD 64
#define M_TOT (BB*SS)        // 126976
#define NPOS (SS*SS)         // 961
#define BH (BB*HH)           // 32768
#define EPS 1e-5f
#define INV_SQRT_C 0.044194173824159216f   // 1/sqrt(512)

// ---------------- scratch (static device memory; no allocations) ----------------
__device__ __align__(16) __half g_xh[(size_t)M_TOT * 512];
__device__ __align__(16) __half g_ctxh[(size_t)M_TOT * 512];
__device__ __align__(16) __half g_qh[(size_t)M_TOT * 512];
__device__ __align__(16) __half g_kh[(size_t)M_TOT * 512];
__device__ __align__(16) __half g_vh[(size_t)M_TOT * 512];
// Weights: per row 1024 halves = [512 hi | 512 lo] (extended-K layout).
__device__ __align__(16) __half g_wh[(size_t)1536 * 1024];
__device__ __align__(16) __half g_woh[(size_t)512 * 1024];

__device__ __align__(16) float g_energy[(size_t)BH * NPOS];

__device__ __align__(16) float g_ch_sum[CC];
__device__ __align__(16) float g_ch_sq[CC];
__device__ __align__(16) float g_scale[CC];
__device__ __align__(16) float g_shift[CC];
__device__ __align__(16) float g_p_sum[NPOS];
__device__ __align__(16) float g_p_sq[NPOS];
__device__ __align__(16) float g_sc2[NPOS];
__device__ __align__(16) float g_sh2[NPOS];

// ---------------- helpers (family-portable mma/ldmatrix/cp.async) ----------------
__device__ __forceinline__ uint32_t smem_u32(const void* p) {
    uint32_t a;
    asm("{ .reg .u64 t; cvta.to.shared.u64 t, %1; cvt.u32.u64 %0, t; }" : "=r"(a) : "l"(p));
    return a;
}
__device__ __forceinline__ void cp16(uint32_t dst, const void* src) {
    asm volatile("cp.async.cg.shared.global [%0], [%1], 16;" :: "r"(dst), "l"(src) : "memory");
}
__device__ __forceinline__ void cp_commit() {
    asm volatile("cp.async.commit_group;" ::: "memory");
}
__device__ __forceinline__ void cp_wait1() {
    asm volatile("cp.async.wait_group 1;" ::: "memory");
}
__device__ __forceinline__ void cp_wait0() {
    asm volatile("cp.async.wait_group 0;" ::: "memory");
}
__device__ __forceinline__ void ldsm_x4(uint32_t* r, uint32_t addr) {
    asm volatile("ldmatrix.sync.aligned.m8n8.x4.shared.b16 {%0,%1,%2,%3}, [%4];"
                 : "=r"(r[0]), "=r"(r[1]), "=r"(r[2]), "=r"(r[3]) : "r"(addr));
}
__device__ __forceinline__ void mma16816(float* c, const uint32_t* a, const uint32_t* b) {
    asm volatile(
        "mma.sync.aligned.m16n8k16.row.col.f32.f16.f16.f32 "
        "{%0,%1,%2,%3}, {%4,%5,%6,%7}, {%8,%9}, {%0,%1,%2,%3};"
        : "+f"(c[0]), "+f"(c[1]), "+f"(c[2]), "+f"(c[3])
        : "r"(a[0]), "r"(a[1]), "r"(a[2]), "r"(a[3]), "r"(b[0]), "r"(b[1]));
}
#define SWZ(off) ((off) ^ (((off) >> 3) & 0x70u))

// ---------------- kernel: zero reduction buffers ----------------
__global__ void k_zero() {
    int i = threadIdx.x;  // <<<1, 1024>>>
    if (i < CC)   { g_ch_sum[i] = 0.f; g_ch_sq[i] = 0.f; }
    if (i < NPOS) { g_p_sum[i] = 0.f;  g_p_sq[i] = 0.f; }
}

// ---------------- kernel: BN1 channel stats ----------------
__global__ void __launch_bounds__(256) k_bn1_stats(const float* __restrict__ x) {
    const int tid = threadIdx.x;
    const size_t r0 = (size_t)blockIdx.x * 128;
    const float* xp = x + r0 * CC;
    float s0 = 0.f, s1 = 0.f, q0 = 0.f, q1 = 0.f;
    for (int r = 0; r < 128; r++) {
        float v0 = xp[(size_t)r * CC + tid];
        float v1 = xp[(size_t)r * CC + tid + 256];
        s0 += v0; q0 += v0 * v0;
        s1 += v1; q1 += v1 * v1;
    }
    atomicAdd(&g_ch_sum[tid],       s0);
    atomicAdd(&g_ch_sq[tid],        q0);
    atomicAdd(&g_ch_sum[tid + 256], s1);
    atomicAdd(&g_ch_sq[tid + 256],  q1);
}

__global__ void k_bn1_fin(const float* __restrict__ nw, const float* __restrict__ nb) {
    int i = blockIdx.x * blockDim.x + threadIdx.x;  // <<<2,256>>>
    if (i >= CC) return;
    float inv_n = 1.0f / (float)M_TOT;
    float mean = g_ch_sum[i] * inv_n;
    float var  = g_ch_sq[i] * inv_n - mean * mean;
    float rs   = rsqrtf(var + EPS);
    float sc   = rs * nw[i];
    g_scale[i] = sc;
    g_shift[i] = nb[i] - mean * sc;
}

// ---------------- prepass: xn = BN(x) -> fp16 ----------------
__global__ void __launch_bounds__(256) k_split_x(const float* __restrict__ x) {
    size_t t = (size_t)blockIdx.x * 256 + threadIdx.x;  // M_TOT*64 threads, 8 elems each
    size_t m = t >> 6;
    int k = (int)(t & 63) * 8;
    const float* xp = x + m * 512 + k;
    float4 a  = *(const float4*)xp;
    float4 b  = *(const float4*)(xp + 4);
    float4 sA = *(const float4*)(g_scale + k);
    float4 sB = *(const float4*)(g_scale + k + 4);
    float4 hA = *(const float4*)(g_shift + k);
    float4 hB = *(const float4*)(g_shift + k + 4);
    __half hb[8];
    hb[0] = __float2half_rn(fmaf(a.x, sA.x, hA.x));
    hb[1] = __float2half_rn(fmaf(a.y, sA.y, hA.y));
    hb[2] = __float2half_rn(fmaf(a.z, sA.z, hA.z));
    hb[3] = __float2half_rn(fmaf(a.w, sA.w, hA.w));
    hb[4] = __float2half_rn(fmaf(b.x, sB.x, hB.x));
    hb[5] = __float2half_rn(fmaf(b.y, sB.y, hB.y));
    hb[6] = __float2half_rn(fmaf(b.z, sB.z, hB.z));
    hb[7] = __float2half_rn(fmaf(b.w, sB.w, hB.w));
    *(uint4*)(g_xh + m * 512 + k) = *(uint4*)hb;
}

// ---------------- prepass: weights fp16 2-term split, [512 hi | 512 lo] rows --------
__global__ void __launch_bounds__(256) k_split_w(const float* __restrict__ Wq,
                                                 const float* __restrict__ Wk,
                                                 const float* __restrict__ Wv,
                                                 const float* __restrict__ Wo) {
    int t = blockIdx.x * 256 + threadIdx.x;  // 2048*64 threads
    int row = t >> 6;
    int k = (t & 63) * 8;
    const float* src;
    __half* base;
    if (row < 1536) {
        src = (row < 512) ? (Wq + (size_t)row * 512)
            : (row < 1024) ? (Wk + (size_t)(row - 512) * 512)
                           : (Wv + (size_t)(row - 1024) * 512);
        base = g_wh + (size_t)row * 1024;
    } else {
        src = Wo + (size_t)(row - 1536) * 512;
        base = g_woh + (size_t)(row - 1536) * 1024;
    }
    float4 a = *(const float4*)(src + k);
    float4 b = *(const float4*)(src + k + 4);
    float v[8] = {a.x, a.y, a.z, a.w, b.x, b.y, b.z, b.w};
    __half hi[8], lo[8];
#pragma unroll
    for (int i = 0; i < 8; i++) {
        hi[i] = __float2half_rn(v[i]);
        lo[i] = __float2half_rn(v[i] - __half2float(hi[i]));
    }
    *(uint4*)(base + k)       = *(uint4*)hi;
    *(uint4*)(base + 512 + k) = *(uint4*)lo;
}

// ---------------- HMMA GEMM: CTA 128x128, 4 warps, extended-K fp16 ----------
// K_ext = 1024: chunks 0-7 = A(0-7) x B_hi, chunks 8-15 = A(0-7) x B_lo.
// MODE 0: A=g_xh, B=g_wh (1536 rows) -> writes g_qh/g_kh/g_vh fp16
// MODE 1: A=g_ctxh, B=g_woh (512 rows) -> out = D + bias + resid (fp32)
template<int MODE>
__global__ void __launch_bounds__(128) k_mma_gemm(const float* __restrict__ bias,
                                                  const float* __restrict__ resid,
                                                  float* __restrict__ Dout) {
    extern __shared__ char sm[];  // 2 stages x (A 16KB + B 16KB) = 64KB
    const int tid = threadIdx.x, lane = tid & 31, w = tid >> 5;
    const int wm = w >> 1, wn = w & 1;
    const int m0 = blockIdx.y * 128, n0g = blockIdx.x * 128;
    const __half* Asrc = (MODE == 0) ? g_xh : g_ctxh;
    const __half* Bsrc = (MODE == 0) ? g_wh : g_woh;
    const uint32_t sbase = smem_u32(sm);

    float c[4][8][4];
#pragma unroll
    for (int i = 0; i < 4; i++)
#pragma unroll
        for (int j = 0; j < 8; j++)
#pragma unroll
            for (int l = 0; l < 4; l++) c[i][j][l] = 0.f;

    const int a_row = lane & 15;
    const int a_cb  = (lane >> 4) * 16;
    const int b_row = (lane & 7) + ((lane >> 4) & 1) * 8;
    const int b_cb  = ((lane >> 3) & 1) * 16;

    auto load_stage = [&](int st, int ch) {
        uint32_t ab = sbase + st * 32768;
        uint32_t bb = ab + 16384;
        const int cha = ch & 7;   // A chunk (reused for hi and lo passes)
#pragma unroll
        for (int j = 0; j < 8; j++) {
            int u = j * 128 + tid, r = u >> 3, q = u & 7;
            cp16(ab + SWZ((uint32_t)(r * 128 + q * 16)),
                 Asrc + (size_t)(m0 + r) * 512 + cha * 64 + q * 8);
        }
#pragma unroll
        for (int j = 0; j < 8; j++) {
            int u = j * 128 + tid, r = u >> 3, q = u & 7;
            cp16(bb + SWZ((uint32_t)(r * 128 + q * 16)),
                 Bsrc + (size_t)(n0g + r) * 1024 + ch * 64 + q * 8);
        }
        cp_commit();
    };

    load_stage(0, 0);

    for (int it = 0; it < 16; it++) {
        if (it + 1 < 16) { load_stage((it + 1) & 1, it + 1); cp_wait1(); }
        else             { cp_wait0(); }
        __syncthreads();

        const uint32_t ab = sbase + (it & 1) * 32768;
        const uint32_t bb = ab + 16384;

#pragma unroll
        for (int ks = 0; ks < 4; ks++) {
            uint32_t a4[4][4], bf[16];
#pragma unroll
            for (int mi = 0; mi < 4; mi++)
                ldsm_x4(a4[mi],
                        ab + SWZ((uint32_t)((wm * 64 + mi * 16 + a_row) * 128 + ks * 32 + a_cb)));
#pragma unroll
            for (int nt = 0; nt < 4; nt++)
                ldsm_x4(&bf[nt * 4],
                        bb + SWZ((uint32_t)((wn * 64 + nt * 16 + b_row) * 128 + ks * 32 + b_cb)));
#pragma unroll
            for (int mi = 0; mi < 4; mi++)
#pragma unroll
                for (int nj = 0; nj < 8; nj++)
                    mma16816(c[mi][nj], a4[mi], &bf[nj * 2]);
        }
        __syncthreads();
    }

    // ---------------- epilogue ----------------
    const int r1 = lane >> 2;
    const int c0 = (lane & 3) * 2;
#pragma unroll
    for (int mi = 0; mi < 4; mi++) {
        const int gr = m0 + wm * 64 + mi * 16;
#pragma unroll
        for (int nj = 0; nj < 8; nj++) {
            const int gc = n0g + wn * 64 + nj * 8 + c0;
            if (MODE == 0) {
                const int sel = gc >> 9;
                const int col = gc & 511;
                __half* op = (sel == 0) ? g_qh : ((sel == 1) ? g_kh : g_vh);
                *(__half2*)(op + (size_t)(gr + r1) * 512 + col) =
                    __floats2half2_rn(c[mi][nj][0], c[mi][nj][1]);
                *(__half2*)(op + (size_t)(gr + r1 + 8) * 512 + col) =
                    __floats2half2_rn(c[mi][nj][2], c[mi][nj][3]);
            } else {
                const int col = gc;
                const float b0 = bias[col], b1 = bias[col + 1];
                {
                    const size_t off = (size_t)(gr + r1) * 512 + col;
                    float2 rv = *(const float2*)(resid + off);
                    *(float2*)(Dout + off) =
                        make_float2(c[mi][nj][0] + b0 + rv.x, c[mi][nj][1] + b1 + rv.y);
                }
                {
                    const size_t off = (size_t)(gr + r1 + 8) * 512 + col;
                    float2 rv = *(const float2*)(resid + off);
                    *(float2*)(Dout + off) =
                        make_float2(c[mi][nj][2] + b0 + rv.x, c[mi][nj][3] + b1 + rv.y);
                }
            }
        }
    }
}

// ---------------- kernel: energy = q . k per (b,h), vectorized ----------------
__global__ void __launch_bounds__(256) k_energy() {
    const int bh = blockIdx.x;
    const int b = bh >> 3, h = bh & 7;
    __shared__ __align__(16) float sq[SS][65];
    __shared__ __align__(16) float skT[64][36];
    const int tid = threadIdx.x;
    const __half* qp = g_qh + (size_t)(b * SS) * 512 + h * 64;
    const __half* kp = g_kh + (size_t)(b * SS) * 512 + h * 64;
    for (int idx = tid; idx < SS * 64; idx += 256) {
        int s = idx >> 6, d = idx & 63;
        sq[s][d]  = __half2float(qp[(size_t)s * 512 + d]);
        skT[d][s] = __half2float(kp[(size_t)s * 512 + d]);
    }
    if (tid < 64) skT[tid][31] = 0.f;
    __syncthreads();
    if (tid < 248) {
        const int i = tid >> 3, j0 = (tid & 7) * 4;
        float4 acc = make_float4(0.f, 0.f, 0.f, 0.f);
#pragma unroll 8
        for (int d = 0; d < 64; d++) {
            float a = sq[i][d];
            float4 kv = *(float4*)&skT[d][j0];
            acc.x = fmaf(a, kv.x, acc.x);
            acc.y = fmaf(a, kv.y, acc.y);
            acc.z = fmaf(a, kv.z, acc.z);
            acc.w = fmaf(a, kv.w, acc.w);
        }
        float* ep = g_energy + (size_t)bh * NPOS + i * SS + j0;
        ep[0] = acc.x; ep[1] = acc.y; ep[2] = acc.z;
        if (j0 < 28) ep[3] = acc.w;
    }
}

// ---------------- kernel: BN2 position stats over (B,H) ----------------
__global__ void __launch_bounds__(256) k_bn2_stats() {
    const int tid = threadIdx.x;
    const size_t r0 = (size_t)blockIdx.x * 128;
    const float* ep = g_energy + r0 * NPOS;
    float s[4] = {0.f, 0.f, 0.f, 0.f};
    float q[4] = {0.f, 0.f, 0.f, 0.f};
    for (int r = 0; r < 128; r++) {
        const float* row = ep + (size_t)r * NPOS;
#pragma unroll
        for (int j = 0; j < 4; j++) {
            int col = tid + j * 256;
            if (col < NPOS) {
                float v = row[col];
                s[j] += v; q[j] += v * v;
            }
        }
    }
#pragma unroll
    for (int j = 0; j < 4; j++) {
        int col = tid + j * 256;
        if (col < NPOS) {
            atomicAdd(&g_p_sum[col], s[j]);
            atomicAdd(&g_p_sq[col],  q[j]);
        }
    }
}

__global__ void k_bn2_fin(const float* __restrict__ pw, const float* __restrict__ pb) {
    int i = blockIdx.x * blockDim.x + threadIdx.x;  // <<<4,256>>>
    if (i >= NPOS) return;
    float inv_n = 1.0f / (float)BH;
    float mean = g_p_sum[i] * inv_n;
    float var  = g_p_sq[i] * inv_n - mean * mean;
    float rs   = rsqrtf(var + EPS);
    float a    = rs * pw[i] * INV_SQRT_C;
    g_sc2[i] = a;
    g_sh2[i] = pb[i] * INV_SQRT_C - mean * a;
}

// ---------------- kernel: softmax + attn @ v per (b,h); writes fp16 ctx ----------------
__global__ void __launch_bounds__(256) k_attn() {
    const int bh = blockIdx.x;
    const int b = bh >> 3, h = bh & 7;
    __shared__ __align__(16) float se[SS * 33];
    __shared__ __align__(16) float sv[SS * 64];
    const int tid = threadIdx.x;
    const float* ep = g_energy + (size_t)bh * NPOS;
    for (int p = tid; p < NPOS; p += 256) {
        int i = p / SS, j = p % SS;
        se[i * 33 + j] = fmaf(ep[p], g_sc2[p], g_sh2[p]);
    }
    const __half* vp = g_vh + (size_t)(b * SS) * 512 + h * 64;
    for (int idx = tid; idx < SS * 64; idx += 256) {
        int s = idx >> 6, d = idx & 63;
        sv[s * 64 + d] = __half2float(vp[(size_t)s * 512 + d]);
    }
    __syncthreads();
    const int w = tid >> 5, l = tid & 31;
    for (int r = w; r < SS; r += 8) {
        float val = (l < SS) ? se[r * 33 + l] : -1e30f;
        float mx = val;
#pragma unroll
        for (int off = 16; off > 0; off >>= 1)
            mx = fmaxf(mx, __shfl_xor_sync(0xFFFFFFFFu, mx, off));
        float pe = (l < SS) ? __expf(val - mx) : 0.f;
        float sum = pe;
#pragma unroll
        for (int off = 16; off > 0; off >>= 1)
            sum += __shfl_xor_sync(0xFFFFFFFFu, sum, off);
        if (l < SS) se[r * 33 + l] = pe / sum;
    }
    __syncthreads();
    for (int u = tid; u < SS * 16; u += 256) {
        const int i = u >> 4, d0 = (u & 15) * 4;
        float4 acc = make_float4(0.f, 0.f, 0.f, 0.f);
#pragma unroll
        for (int lk = 0; lk < SS; lk++) {
            float p = se[i * 33 + lk];
            float4 vv = *(float4*)&sv[lk * 64 + d0];
            acc.x = fmaf(p, vv.x, acc.x);
            acc.y = fmaf(p, vv.y, acc.y);
            acc.z = fmaf(p, vv.z, acc.z);
            acc.w = fmaf(p, vv.w, acc.w);
        }
        __half hb[4];
        hb[0] = __float2half_rn(acc.x);
        hb[1] = __float2half_rn(acc.y);
        hb[2] = __float2half_rn(acc.z);
        hb[3] = __float2half_rn(acc.w);
        *(uint2*)(g_ctxh + (size_t)(b * SS + i) * 512 + h * 64 + d0) = *(uint2*)hb;
    }
}

// ---------------- launch ----------------
extern "C" void kernel_launch(void* const* d_in, const int* in_sizes, int n_in,
                              void* d_out, int out_size) {
    const float* x     = (const float*)d_in[0];
    const float* nw    = (const float*)d_in[1];
    const float* nbias = (const float*)d_in[2];
    const float* Wq    = (const float*)d_in[3];
    const float* Wk    = (const float*)d_in[4];
    const float* Wv    = (const float*)d_in[5];
    const float* Wout  = (const float*)d_in[6];
    const float* b_out = (const float*)d_in[7];
    const float* pw    = (const float*)d_in[8];
    const float* pb    = (const float*)d_in[9];
    float* out = (float*)d_out;

    cudaFuncSetAttribute(k_mma_gemm<0>, cudaFuncAttributeMaxDynamicSharedMemorySize, 65536);
    cudaFuncSetAttribute(k_mma_gemm<1>, cudaFuncAttributeMaxDynamicSharedMemorySize, 65536);

    k_zero<<<1, 1024>>>();
    k_split_w<<<512, 256>>>(Wq, Wk, Wv, Wout);
    k_bn1_stats<<<M_TOT / 128, 256>>>(x);
    k_bn1_fin<<<2, 256>>>(nw, nbias);
    k_split_x<<<M_TOT / 4, 256>>>(x);

    k_mma_gemm<0><<<dim3(12, 992), 128, 65536>>>(nullptr, nullptr, nullptr);

    k_energy<<<BH, 256>>>();
    k_bn2_stats<<<BH / 128, 256>>>();
    k_bn2_fin<<<4, 256>>>(pw, pb);
    k_attn<<<BH, 256>>>();

    k_mma_gemm<1><<<dim3(4, 992), 128, 65536>>>(b_out, x, out);
}

// round 7
// speedup vs baseline: 1.1255x; 1.1255x over previous
#include <cuda_runtime.h>
#include <cuda_bf16.h>
#include <cstdint>

// Problem constants
#define BB 4096
#define SS 31
#define CC 512
#define HH 8
#define HD 64
#define M_TOT (BB*SS)        // 126976
#define NPOS (SS*SS)         // 961
#define BH (BB*HH)           // 32768
#define EPS 1e-5f
#define INV_SQRT_C 0.044194173824159216f   // 1/sqrt(512)

// ---------------- scratch (static device memory; no allocations) ----------------
// Packed bf16-split layout: per row of 512, 16 chunks; each chunk = 64 bf16 = [32 hi | 32 lo] (128 B).
__device__ __align__(16) __nv_bfloat16 g_xp[(size_t)M_TOT * 1024];
__device__ __align__(16) __nv_bfloat16 g_ctxp[(size_t)M_TOT * 1024];
__device__ __align__(16) __nv_bfloat16 g_wp[(size_t)1536 * 1024];
__device__ __align__(16) __nv_bfloat16 g_wop[(size_t)512 * 1024];

__device__ __align__(16) float g_q[(size_t)M_TOT * CC];
__device__ __align__(16) float g_k[(size_t)M_TOT * CC];
__device__ __align__(16) float g_v[(size_t)M_TOT * CC];
__device__ __align__(16) float g_energy[(size_t)BH * NPOS];

__device__ __align__(16) float g_ch_sum[CC];
__device__ __align__(16) float g_ch_sq[CC];
__device__ __align__(16) float g_scale[CC];
__device__ __align__(16) float g_shift[CC];
__device__ __align__(16) float g_p_sum[NPOS];
__device__ __align__(16) float g_p_sq[NPOS];
__device__ __align__(16) float g_sc2[NPOS];
__device__ __align__(16) float g_sh2[NPOS];

// ---------------- helpers (family-portable mma/ldmatrix/cp.async) ----------------
__device__ __forceinline__ uint32_t smem_u32(const void* p) {
    uint32_t a;
    asm("{ .reg .u64 t; cvta.to.shared.u64 t, %1; cvt.u32.u64 %0, t; }" : "=r"(a) : "l"(p));
    return a;
}
__device__ __forceinline__ void cp16(uint32_t dst, const void* src) {
    asm volatile("cp.async.cg.shared.global [%0], [%1], 16;" :: "r"(dst), "l"(src) : "memory");
}
__device__ __forceinline__ void cp_commit() {
    asm volatile("cp.async.commit_group;" ::: "memory");
}
__device__ __forceinline__ void cp_wait1() {
    asm volatile("cp.async.wait_group 1;" ::: "memory");
}
__device__ __forceinline__ void cp_wait0() {
    asm volatile("cp.async.wait_group 0;" ::: "memory");
}
__device__ __forceinline__ void ldsm_x4(uint32_t* r, uint32_t addr) {
    asm volatile("ldmatrix.sync.aligned.m8n8.x4.shared.b16 {%0,%1,%2,%3}, [%4];"
                 : "=r"(r[0]), "=r"(r[1]), "=r"(r[2]), "=r"(r[3]) : "r"(addr));
}
__device__ __forceinline__ void mma16816(float* c, const uint32_t* a, const uint32_t* b) {
    asm volatile(
        "mma.sync.aligned.m16n8k16.row.col.f32.bf16.bf16.f32 "
        "{%0,%1,%2,%3}, {%4,%5,%6,%7}, {%8,%9}, {%0,%1,%2,%3};"
        : "+f"(c[0]), "+f"(c[1]), "+f"(c[2]), "+f"(c[3])
        : "r"(a[0]), "r"(a[1]), "r"(a[2]), "r"(a[3]), "r"(b[0]), "r"(b[1]));
}
#define SWZ(off) ((off) ^ (((off) >> 3) & 0x70u))

// ---------------- kernel: zero reduction buffers ----------------
__global__ void k_zero() {
    int i = threadIdx.x;  // <<<1, 1024>>>
    if (i < CC)   { g_ch_sum[i] = 0.f; g_ch_sq[i] = 0.f; }
    if (i < NPOS) { g_p_sum[i] = 0.f;  g_p_sq[i] = 0.f; }
}

// ---------------- kernel: BN1 channel stats ----------------
__global__ void __launch_bounds__(256) k_bn1_stats(const float* __restrict__ x) {
    const int tid = threadIdx.x;
    const size_t r0 = (size_t)blockIdx.x * 128;
    const float* xp = x + r0 * CC;
    float s0 = 0.f, s1 = 0.f, q0 = 0.f, q1 = 0.f;
    for (int r = 0; r < 128; r++) {
        float v0 = xp[(size_t)r * CC + tid];
        float v1 = xp[(size_t)r * CC + tid + 256];
        s0 += v0; q0 += v0 * v0;
        s1 += v1; q1 += v1 * v1;
    }
    atomicAdd(&g_ch_sum[tid],       s0);
    atomicAdd(&g_ch_sq[tid],        q0);
    atomicAdd(&g_ch_sum[tid + 256], s1);
    atomicAdd(&g_ch_sq[tid + 256],  q1);
}

__global__ void k_bn1_fin(const float* __restrict__ nw, const float* __restrict__ nb) {
    int i = blockIdx.x * blockDim.x + threadIdx.x;  // <<<2,256>>>
    if (i >= CC) return;
    float inv_n = 1.0f / (float)M_TOT;
    float mean = g_ch_sum[i] * inv_n;
    float var  = g_ch_sq[i] * inv_n - mean * mean;
    float rs   = rsqrtf(var + EPS);
    float sc   = rs * nw[i];
    g_scale[i] = sc;
    g_shift[i] = nb[i] - mean * sc;
}

// ---------------- prepass: xn = BN(x), bf16-split, packed ----------------
__global__ void __launch_bounds__(256) k_split_x(const float* __restrict__ x) {
    size_t t = (size_t)blockIdx.x * 256 + threadIdx.x;  // M_TOT*64 threads, 8 elems each
    size_t m = t >> 6;
    int oct = (int)(t & 63);
    int c = oct >> 2, pos = (oct & 3) << 3, k = oct << 3;
    const float* xp = x + m * 512 + k;
    float4 a  = *(const float4*)xp;
    float4 b  = *(const float4*)(xp + 4);
    float4 sA = *(const float4*)(g_scale + k);
    float4 sB = *(const float4*)(g_scale + k + 4);
    float4 hA = *(const float4*)(g_shift + k);
    float4 hB = *(const float4*)(g_shift + k + 4);
    float v[8];
    v[0] = fmaf(a.x, sA.x, hA.x); v[1] = fmaf(a.y, sA.y, hA.y);
    v[2] = fmaf(a.z, sA.z, hA.z); v[3] = fmaf(a.w, sA.w, hA.w);
    v[4] = fmaf(b.x, sB.x, hB.x); v[5] = fmaf(b.y, sB.y, hB.y);
    v[6] = fmaf(b.z, sB.z, hB.z); v[7] = fmaf(b.w, sB.w, hB.w);
    __nv_bfloat16 hi[8], lo[8];
#pragma unroll
    for (int i = 0; i < 8; i++) {
        hi[i] = __float2bfloat16(v[i]);
        lo[i] = __float2bfloat16(v[i] - __bfloat162float(hi[i]));
    }
    __nv_bfloat16* dst = g_xp + ((m * 16 + c) << 6) + pos;
    *(uint4*)dst        = *(uint4*)hi;
    *(uint4*)(dst + 32) = *(uint4*)lo;
}

// ---------------- prepass: weights bf16-split, packed ----------------
__global__ void __launch_bounds__(256) k_split_w(const float* __restrict__ Wq,
                                                 const float* __restrict__ Wk,
                                                 const float* __restrict__ Wv,
                                                 const float* __restrict__ Wo) {
    int t = blockIdx.x * 256 + threadIdx.x;  // (1536+512)*64 threads
    int row = t >> 6;
    int oct = t & 63;
    int c = oct >> 2, pos = (oct & 3) << 3, k = oct << 3;
    const float* src;
    __nv_bfloat16* dst;
    if (row < 1536) {
        src = (row < 512) ? (Wq + (size_t)row * 512)
            : (row < 1024) ? (Wk + (size_t)(row - 512) * 512)
                           : (Wv + (size_t)(row - 1024) * 512);
        dst = g_wp + (((size_t)row * 16 + c) << 6) + pos;
    } else {
        int r2 = row - 1536;
        src = Wo + (size_t)r2 * 512;
        dst = g_wop + (((size_t)r2 * 16 + c) << 6) + pos;
    }
    float4 a = *(const float4*)(src + k);
    float4 b = *(const float4*)(src + k + 4);
    float v[8] = {a.x, a.y, a.z, a.w, b.x, b.y, b.z, b.w};
    __nv_bfloat16 hi[8], lo[8];
#pragma unroll
    for (int i = 0; i < 8; i++) {
        hi[i] = __float2bfloat16(v[i]);
        lo[i] = __float2bfloat16(v[i] - __bfloat162float(hi[i]));
    }
    *(uint4*)dst        = *(uint4*)hi;
    *(uint4*)(dst + 32) = *(uint4*)lo;
}

// ---------------- HMMA GEMM: CTA 128x128, 8 warps (32x64 each), 3-term bf16 ----------
// MODE 0: A = g_xp, B = g_wp (1536 rows) -> writes g_q/g_k/g_v fp32
// MODE 1: A = g_ctxp, B = g_wop (512 rows) -> out = D + bias + resid
template<int MODE>
__global__ void __launch_bounds__(256) k_mma_gemm(const float* __restrict__ bias,
                                                  const float* __restrict__ resid,
                                                  float* __restrict__ Dout) {
    extern __shared__ char sm[];  // 2 stages x (A 16KB + B 16KB) = 64KB
    const int tid = threadIdx.x, lane = tid & 31, w = tid >> 5;
    const int wm = w & 3, wn = w >> 2;          // 4 m-tiles of 32 rows, 2 n-tiles of 64 cols
    const int m0 = blockIdx.y * 128, n0g = blockIdx.x * 128;
    const __nv_bfloat16* Asrc = (MODE == 0) ? g_xp : g_ctxp;
    const __nv_bfloat16* Bsrc = (MODE == 0) ? g_wp : g_wop;
    const uint32_t sbase = smem_u32(sm);

    float c[2][8][4];
#pragma unroll
    for (int i = 0; i < 2; i++)
#pragma unroll
        for (int j = 0; j < 8; j++)
#pragma unroll
            for (int l = 0; l < 4; l++) c[i][j][l] = 0.f;

    // lane addressing for ldmatrix
    const int a_row = lane & 15;
    const int a_cb  = (lane >> 4) * 16;
    const int b_row = (lane & 7) + ((lane >> 4) & 1) * 8;
    const int b_cb  = ((lane >> 3) & 1) * 16;

    // --- stage loader (256 threads: 4 uint4 each for A, 4 for B) ---
    auto load_stage = [&](int st, int ch) {
        uint32_t abase = sbase + st * 32768;
        uint32_t bbase = abase + 16384;
#pragma unroll
        for (int j = 0; j < 4; j++) {
            int u = j * 256 + tid, r = u >> 3, q = u & 7;
            cp16(abase + SWZ((uint32_t)(r * 128 + q * 16)),
                 Asrc + (((size_t)(m0 + r) * 16 + ch) << 6) + q * 8);
        }
#pragma unroll
        for (int j = 0; j < 4; j++) {
            int u = j * 256 + tid, r = u >> 3, q = u & 7;
            cp16(bbase + SWZ((uint32_t)(r * 128 + q * 16)),
                 Bsrc + (((size_t)(n0g + r) * 16 + ch) << 6) + q * 8);
        }
        cp_commit();
    };

    load_stage(0, 0);

    for (int it = 0; it < 16; it++) {
        if (it + 1 < 16) { load_stage((it + 1) & 1, it + 1); cp_wait1(); }
        else             { cp_wait0(); }
        __syncthreads();

        const uint32_t abase = sbase + (it & 1) * 32768;
        const uint32_t bbase = abase + 16384;

#pragma unroll
        for (int ks = 0; ks < 2; ks++) {
            uint32_t ah[8], al[8], bh[16], bl[16];
            // hi A fragments (2 m16 tiles)
#pragma unroll
            for (int mi = 0; mi < 2; mi++)
                ldsm_x4(&ah[mi * 4],
                        abase + SWZ((uint32_t)((wm * 32 + mi * 16 + a_row) * 128 + ks * 32 + a_cb)));
            // hi B fragments (4 n16 tiles covering 64 n)
#pragma unroll
            for (int nt = 0; nt < 4; nt++)
                ldsm_x4(&bh[nt * 4],
                        bbase + SWZ((uint32_t)((wn * 64 + nt * 16 + b_row) * 128 + ks * 32 + b_cb)));
            // term 1: hiA x hiB
#pragma unroll
            for (int mi = 0; mi < 2; mi++)
#pragma unroll
                for (int nj = 0; nj < 8; nj++)
                    mma16816(c[mi][nj], &ah[mi * 4], &bh[nj * 2]);
            // lo B
#pragma unroll
            for (int nt = 0; nt < 4; nt++)
                ldsm_x4(&bl[nt * 4],
                        bbase + SWZ((uint32_t)((wn * 64 + nt * 16 + b_row) * 128 + 64 + ks * 32 + b_cb)));
            // term 2: hiA x loB
#pragma unroll
            for (int mi = 0; mi < 2; mi++)
#pragma unroll
                for (int nj = 0; nj < 8; nj++)
                    mma16816(c[mi][nj], &ah[mi * 4], &bl[nj * 2]);
            // lo A
#pragma unroll
            for (int mi = 0; mi < 2; mi++)
                ldsm_x4(&al[mi * 4],
                        abase + SWZ((uint32_t)((wm * 32 + mi * 16 + a_row) * 128 + 64 + ks * 32 + a_cb)));
            // term 3: loA x hiB
#pragma unroll
            for (int mi = 0; mi < 2; mi++)
#pragma unroll
                for (int nj = 0; nj < 8; nj++)
                    mma16816(c[mi][nj], &al[mi * 4], &bh[nj * 2]);
        }
        __syncthreads();
    }

    // ---------------- epilogue: register fragments -> global ----------------
    const int r1 = lane >> 2;
    const int c0 = (lane & 3) * 2;
#pragma unroll
    for (int mi = 0; mi < 2; mi++) {
        const int gr = m0 + wm * 32 + mi * 16;
#pragma unroll
        for (int nj = 0; nj < 8; nj++) {
            const int gc = n0g + wn * 64 + nj * 8 + c0;
            if (MODE == 0) {
                const int sel = gc >> 9;
                const int col = gc & 511;
                float* op = (sel == 0) ? g_q : ((sel == 1) ? g_k : g_v);
                *(float2*)(op + (size_t)(gr + r1) * 512 + col) =
                    make_float2(c[mi][nj][0], c[mi][nj][1]);
                *(float2*)(op + (size_t)(gr + r1 + 8) * 512 + col) =
                    make_float2(c[mi][nj][2], c[mi][nj][3]);
            } else {
                const int col = gc;
                const float b0 = bias[col], b1 = bias[col + 1];
                {
                    const size_t off = (size_t)(gr + r1) * 512 + col;
                    float2 rv = *(const float2*)(resid + off);
                    *(float2*)(Dout + off) =
                        make_float2(c[mi][nj][0] + b0 + rv.x, c[mi][nj][1] + b1 + rv.y);
                }
                {
                    const size_t off = (size_t)(gr + r1 + 8) * 512 + col;
                    float2 rv = *(const float2*)(resid + off);
                    *(float2*)(Dout + off) =
                        make_float2(c[mi][nj][2] + b0 + rv.x, c[mi][nj][3] + b1 + rv.y);
                }
            }
        }
    }
}

// ---------------- kernel: energy = q . k per (b,h) ----------------
__global__ void __launch_bounds__(256) k_energy() {
    const int bh = blockIdx.x;
    const int b = bh >> 3, h = bh & 7;
    __shared__ float sq[SS * 65];
    __shared__ float sk[SS * 65];
    const int tid = threadIdx.x;
    const float* qp = g_q + (size_t)(b * SS) * CC + h * HD;
    const float* kp = g_k + (size_t)(b * SS) * CC + h * HD;
    for (int idx = tid; idx < SS * HD; idx += 256) {
        int s = idx / HD, d = idx % HD;
        sq[s * 65 + d] = qp[(size_t)s * CC + d];
        sk[s * 65 + d] = kp[(size_t)s * CC + d];
    }
    __syncthreads();
    float* ep = g_energy + (size_t)bh * NPOS;
    for (int p = tid; p < NPOS; p += 256) {
        int i = p / SS, j = p % SS;
        float accv = 0.f;
#pragma unroll
        for (int d = 0; d < HD; d++) accv += sq[i * 65 + d] * sk[j * 65 + d];
        ep[p] = accv;
    }
}

// ---------------- kernel: BN2 position stats over (B,H) ----------------
__global__ void __launch_bounds__(256) k_bn2_stats() {
    const int tid = threadIdx.x;
    const size_t r0 = (size_t)blockIdx.x * 128;
    const float* ep = g_energy + r0 * NPOS;
    float s[4] = {0.f, 0.f, 0.f, 0.f};
    float q[4] = {0.f, 0.f, 0.f, 0.f};
    for (int r = 0; r < 128; r++) {
        const float* row = ep + (size_t)r * NPOS;
#pragma unroll
        for (int j = 0; j < 4; j++) {
            int col = tid + j * 256;
            if (col < NPOS) {
                float v = row[col];
                s[j] += v; q[j] += v * v;
            }
        }
    }
#pragma unroll
    for (int j = 0; j < 4; j++) {
        int col = tid + j * 256;
        if (col < NPOS) {
            atomicAdd(&g_p_sum[col], s[j]);
            atomicAdd(&g_p_sq[col],  q[j]);
        }
    }
}

__global__ void k_bn2_fin(const float* __restrict__ pw, const float* __restrict__ pb) {
    int i = blockIdx.x * blockDim.x + threadIdx.x;  // <<<4,256>>>
    if (i >= NPOS) return;
    float inv_n = 1.0f / (float)BH;
    float mean = g_p_sum[i] * inv_n;
    float var  = g_p_sq[i] * inv_n - mean * mean;
    float rs   = rsqrtf(var + EPS);
    float a    = rs * pw[i] * INV_SQRT_C;
    g_sc2[i] = a;
    g_sh2[i] = pb[i] * INV_SQRT_C - mean * a;
}

// ---------------- kernel: softmax + attn @ v per (b,h); writes split ctx ----------------
__global__ void __launch_bounds__(256) k_attn() {
    const int bh = blockIdx.x;
    const int b = bh >> 3, h = bh & 7;
    __shared__ float se[SS * 32];
    __shared__ float sv[SS * HD];
    const int tid = threadIdx.x;
    const float* ep = g_energy + (size_t)bh * NPOS;
    for (int p = tid; p < NPOS; p += 256) {
        int i = p / SS, j = p % SS;
        se[i * 32 + j] = fmaf(ep[p], g_sc2[p], g_sh2[p]);
    }
    const float* vp = g_v + (size_t)(b * SS) * CC + h * HD;
    for (int idx = tid; idx < SS * HD; idx += 256) {
        int s = idx / HD, d = idx % HD;
        sv[s * HD + d] = vp[(size_t)s * CC + d];
    }
    __syncthreads();
    const int w = tid >> 5, l = tid & 31;
    for (int r = w; r < SS; r += 8) {
        float val = (l < SS) ? se[r * 32 + l] : -1e30f;
        float mx = val;
#pragma unroll
        for (int off = 16; off > 0; off >>= 1)
            mx = fmaxf(mx, __shfl_xor_sync(0xFFFFFFFFu, mx, off));
        float pe = (l < SS) ? __expf(val - mx) : 0.f;
        float sum = pe;
#pragma unroll
        for (int off = 16; off > 0; off >>= 1)
            sum += __shfl_xor_sync(0xFFFFFFFFu, sum, off);
        if (l < SS) se[r * 32 + l] = pe / sum;
    }
    __syncthreads();
    for (int idx = tid; idx < SS * HD; idx += 256) {
        int i = idx / HD, d = idx % HD;
        float accv = 0.f;
#pragma unroll
        for (int lk = 0; lk < SS; lk++) accv += se[i * 32 + lk] * sv[lk * HD + d];
        __nv_bfloat16 hi = __float2bfloat16(accv);
        __nv_bfloat16 lo = __float2bfloat16(accv - __bfloat162float(hi));
        int colg = h * HD + d;
        int c = colg >> 5, pos = colg & 31;
        size_t base = (((size_t)(b * SS + i) * 16 + c) << 6) + pos;
        g_ctxp[base]      = hi;
        g_ctxp[base + 32] = lo;
    }
}

// ---------------- launch ----------------
extern "C" void kernel_launch(void* const* d_in, const int* in_sizes, int n_in,
                              void* d_out, int out_size) {
    const float* x     = (const float*)d_in[0];
    const float* nw    = (const float*)d_in[1];
    const float* nbias = (const float*)d_in[2];
    const float* Wq    = (const float*)d_in[3];
    const float* Wk    = (const float*)d_in[4];
    const float* Wv    = (const float*)d_in[5];
    const float* Wout  = (const float*)d_in[6];
    const float* b_out = (const float*)d_in[7];
    const float* pw    = (const float*)d_in[8];
    const float* pb    = (const float*)d_in[9];
    float* out = (float*)d_out;

    cudaFuncSetAttribute(k_mma_gemm<0>, cudaFuncAttributeMaxDynamicSharedMemorySize, 65536);
    cudaFuncSetAttribute(k_mma_gemm<1>, cudaFuncAttributeMaxDynamicSharedMemorySize, 65536);

    k_zero<<<1, 1024>>>();
    k_split_w<<<512, 256>>>(Wq, Wk, Wv, Wout);
    k_bn1_stats<<<M_TOT / 128, 256>>>(x);
    k_bn1_fin<<<2, 256>>>(nw, nbias);
    k_split_x<<<M_TOT / 4, 256>>>(x);

    k_mma_gemm<0><<<dim3(12, 992), 256, 65536>>>(nullptr, nullptr, nullptr);

    k_energy<<<BH, 256>>>();
    k_bn2_stats<<<BH / 128, 256>>>();
    k_bn2_fin<<<4, 256>>>(pw, pb);
    k_attn<<<BH, 256>>>();

    k_mma_gemm<1><<<dim3(4, 992), 256, 65536>>>(b_out, x, out);
}